// round 4
// baseline (speedup 1.0000x reference)
#include <cuda_runtime.h>
#include <cstdint>
#include <math.h>

#define NTOK 32768          // B * C * T = 8 * 64 * 64
#define DM   768
#define DQKV 2304
#define DFC  3072

// ---------------- scratch (device globals; no allocations) ----------------
__device__ __align__(16) float  g_f[(size_t)NTOK * DM];
__device__ __align__(16) float  g_qkv[(size_t)NTOK * DQKV];
__device__ __align__(16) float  g_x2[(size_t)NTOK * DM];
__device__ __align__(16) float  g_fc1[(size_t)NTOK * DFC];
__device__ __align__(16) int8_t g_q[(size_t)NTOK * DM];
__device__ __align__(16) int8_t g_fc1q[(size_t)NTOK * DFC];
__device__ __align__(16) int8_t g_wqkv[DQKV * DM];
__device__ __align__(16) int8_t g_wproj[DM * DM];
__device__ __align__(16) int8_t g_wfc1[DFC * DM];
__device__ __align__(16) int8_t g_wfc2[DM * DFC];
__device__ __align__(16) float  g_amax[16];   // 0 ln1 1 attn 2 ln2 3 gelu 4..7 weights
__device__ __align__(16) float  g_slots[3 * 2048]; // spread amax slots (32 used, stride 64)

__device__ __forceinline__ void atomicMaxF(float* a, float v) {
    atomicMax(reinterpret_cast<unsigned int*>(a), __float_as_uint(v)); // v >= 0
}
__device__ __forceinline__ uint32_t smem_u32(const void* p) {
    return (uint32_t)__cvta_generic_to_shared(p);
}
__device__ __forceinline__ void cp16(uint32_t dst, const void* src) {
    asm volatile("cp.async.cg.shared.global [%0], [%1], 16;\n" :: "r"(dst), "l"(src));
}
__device__ __forceinline__ void mma_s8(int* c, const int* a, int b0, int b1) {
    asm volatile(
        "mma.sync.aligned.m16n8k32.row.col.s32.s8.s8.s32 "
        "{%0,%1,%2,%3}, {%4,%5,%6,%7}, {%8,%9}, {%0,%1,%2,%3};\n"
        : "+r"(c[0]), "+r"(c[1]), "+r"(c[2]), "+r"(c[3])
        : "r"(a[0]), "r"(a[1]), "r"(a[2]), "r"(a[3]), "r"(b0), "r"(b1));
}
__device__ __forceinline__ void ldsm4(uint32_t a, int* r) {
    asm volatile("ldmatrix.sync.aligned.m8n8.x4.shared.b16 {%0,%1,%2,%3}, [%4];"
                 : "=r"(r[0]), "=r"(r[1]), "=r"(r[2]), "=r"(r[3]) : "r"(a));
}
__device__ __forceinline__ uint32_t pack4(float4 v, float s) {
    int i0 = (int)fminf(fmaxf(rintf(__fdiv_rn(v.x, s)), -128.0f), 127.0f);
    int i1 = (int)fminf(fmaxf(rintf(__fdiv_rn(v.y, s)), -128.0f), 127.0f);
    int i2 = (int)fminf(fmaxf(rintf(__fdiv_rn(v.z, s)), -128.0f), 127.0f);
    int i3 = (int)fminf(fmaxf(rintf(__fdiv_rn(v.w, s)), -128.0f), 127.0f);
    return (uint32_t)(i0 & 255) | ((uint32_t)(i1 & 255) << 8) |
           ((uint32_t)(i2 & 255) << 16) | ((uint32_t)(i3 & 255) << 24);
}

// ---------------- init / reduce ----------------
__global__ void zero_k(float* amax, float* slots) {
    int i = blockIdx.x * blockDim.x + threadIdx.x;
    if (i < 16) amax[i] = 0.0f;
    for (int j = i; j < 3 * 2048; j += gridDim.x * blockDim.x) slots[j] = 0.0f;
}

__global__ void reduce_amax_k(const float* __restrict__ slots, float* __restrict__ dst) {
    float v = slots[threadIdx.x * 64];
#pragma unroll
    for (int o = 16; o > 0; o >>= 1) v = fmaxf(v, __shfl_xor_sync(0xffffffffu, v, o));
    if (threadIdx.x == 0) dst[0] = v;
}

// ---------------- weight absmax (segmented, float4) ----------------
__global__ __launch_bounds__(256) void absmax_w_k(
    const float* __restrict__ w0, const float* __restrict__ w1,
    const float* __restrict__ w2, const float* __restrict__ w3, float* __restrict__ amax)
{
    const float* w; int n4;
    switch (blockIdx.y) {
        case 0: w = w0; n4 = DQKV * DM / 4; break;
        case 1: w = w1; n4 = DM * DM / 4;   break;
        case 2: w = w2; n4 = DFC * DM / 4;  break;
        default: w = w3; n4 = DM * DFC / 4; break;
    }
    float m = 0.0f;
#pragma unroll 4
    for (int i = blockIdx.x * 256 + threadIdx.x; i < n4; i += gridDim.x * 256) {
        float4 v = reinterpret_cast<const float4*>(w)[i];
        m = fmaxf(m, fmaxf(fmaxf(fabsf(v.x), fabsf(v.y)), fmaxf(fabsf(v.z), fabsf(v.w))));
    }
#pragma unroll
    for (int o = 16; o > 0; o >>= 1) m = fmaxf(m, __shfl_xor_sync(0xffffffffu, m, o));
    __shared__ float sm[8];
    if ((threadIdx.x & 31) == 0) sm[threadIdx.x >> 5] = m;
    __syncthreads();
    if (threadIdx.x == 0) {
        float t = sm[0];
#pragma unroll
        for (int k = 1; k < 8; k++) t = fmaxf(t, sm[k]);
        atomicMaxF(&amax[4 + blockIdx.y], t);
    }
}

// ---------------- weight quantize (segmented, float4 -> uint32) ----------------
__global__ __launch_bounds__(256) void quant_w_k(
    const float* __restrict__ w0, const float* __restrict__ w1,
    const float* __restrict__ w2, const float* __restrict__ w3,
    int8_t* __restrict__ q0, int8_t* __restrict__ q1,
    int8_t* __restrict__ q2, int8_t* __restrict__ q3, const float* __restrict__ amax)
{
    const float* w; int8_t* q; int n4;
    switch (blockIdx.y) {
        case 0: w = w0; q = q0; n4 = DQKV * DM / 4; break;
        case 1: w = w1; q = q1; n4 = DM * DM / 4;   break;
        case 2: w = w2; q = q2; n4 = DFC * DM / 4;  break;
        default: w = w3; q = q3; n4 = DM * DFC / 4; break;
    }
    float s = __fdiv_rn(fmaxf(amax[4 + blockIdx.y], 1e-8f), 127.0f);
#pragma unroll 4
    for (int i = blockIdx.x * 256 + threadIdx.x; i < n4; i += gridDim.x * 256)
        reinterpret_cast<uint32_t*>(q)[i] = pack4(reinterpret_cast<const float4*>(w)[i], s);
}

// ---------------- activation quantize (float4 -> uint32) ----------------
__global__ __launch_bounds__(256) void quant_a_k(const float* __restrict__ x,
                                                 int8_t* __restrict__ q, int n4,
                                                 const float* __restrict__ amax) {
    float s = __fdiv_rn(fmaxf(amax[0], 1e-8f), 127.0f);
#pragma unroll 4
    for (int i = blockIdx.x * 256 + threadIdx.x; i < n4; i += gridDim.x * 256)
        reinterpret_cast<uint32_t*>(q)[i] = pack4(reinterpret_cast<const float4*>(x)[i], s);
}

// ---------------- layernorm + fused absmax (warp-shuffle reductions) ----------------
__global__ __launch_bounds__(256) void ln_k(const float* __restrict__ x,
                                            const float* __restrict__ g,
                                            const float* __restrict__ b,
                                            float* __restrict__ out,
                                            float* __restrict__ slot) {
    __shared__ float sm[8];
    __shared__ float bc[2];
    int row = blockIdx.x, tid = threadIdx.x;
    int lane = tid & 31, wid = tid >> 5;
    const float* xr = x + (size_t)row * DM;
    float v0 = xr[tid], v1 = xr[tid + 256], v2 = xr[tid + 512];

    float s = v0 + v1 + v2;
#pragma unroll
    for (int o = 16; o > 0; o >>= 1) s += __shfl_xor_sync(0xffffffffu, s, o);
    if (lane == 0) sm[wid] = s;
    __syncthreads();
    if (wid == 0) {
        float t = (lane < 8) ? sm[lane] : 0.0f;
#pragma unroll
        for (int o = 4; o > 0; o >>= 1) t += __shfl_xor_sync(0xffffffffu, t, o);
        if (lane == 0) bc[0] = t * (1.0f / 768.0f);
    }
    __syncthreads();
    float mean = bc[0];
    float d0 = v0 - mean, d1 = v1 - mean, d2 = v2 - mean;
    float ss = d0 * d0 + d1 * d1 + d2 * d2;
#pragma unroll
    for (int o = 16; o > 0; o >>= 1) ss += __shfl_xor_sync(0xffffffffu, ss, o);
    if (lane == 0) sm[wid] = ss;
    __syncthreads();
    if (wid == 0) {
        float t = (lane < 8) ? sm[lane] : 0.0f;
#pragma unroll
        for (int o = 4; o > 0; o >>= 1) t += __shfl_xor_sync(0xffffffffu, t, o);
        if (lane == 0) bc[1] = __frsqrt_rn(t * (1.0f / 768.0f) + 1e-5f);
    }
    __syncthreads();
    float rs = bc[1];
    float o0 = d0 * rs * g[tid]       + b[tid];
    float o1 = d1 * rs * g[tid + 256] + b[tid + 256];
    float o2 = d2 * rs * g[tid + 512] + b[tid + 512];
    float* orow = out + (size_t)row * DM;
    orow[tid] = o0; orow[tid + 256] = o1; orow[tid + 512] = o2;

    float lm = fmaxf(fmaxf(fabsf(o0), fabsf(o1)), fabsf(o2));
#pragma unroll
    for (int o = 16; o > 0; o >>= 1) lm = fmaxf(lm, __shfl_xor_sync(0xffffffffu, lm, o));
    if (lane == 0) sm[wid] = lm;
    __syncthreads();
    if (tid == 0) {
        float t = sm[0];
#pragma unroll
        for (int k = 1; k < 8; k++) t = fmaxf(t, sm[k]);
        atomicMaxF(slot + (row & 31) * 64, t);
    }
}

// ---------------- int8 IMMA GEMM with ldmatrix, C = A[M,K] * B[N,K]^T ----------------
// Block 128x128, BK=64, 2-stage cp.async, XOR swizzle (((row>>1)&3)<<4 on 16B chunks).
// EPI: 0 = bias, 1 = bias + residual, 2 = bias + exact GELU + fused absmax
template<int EPI>
__global__ __launch_bounds__(256, 2) void gemm_imma_k(
    const int8_t* __restrict__ A, const int8_t* __restrict__ B,
    int M, int N, int K,
    const float* __restrict__ amaxA, const float* __restrict__ amaxB,
    const float* __restrict__ bias, const float* __restrict__ res,
    float* __restrict__ C, float* __restrict__ gmax)
{
    __shared__ int sA[2][128 * 16];
    __shared__ int sB[2][128 * 16];
    const int tid  = threadIdx.x;
    const int lane = tid & 31, warp = tid >> 5;
    const int wm = warp & 3, wn = warp >> 2;
    const int m0 = blockIdx.y * 128, n0 = blockIdx.x * 128;
    const int gid = lane >> 2, tig = lane & 3;

    int acc[2][8][4];
#pragma unroll
    for (int mi = 0; mi < 2; mi++)
#pragma unroll
        for (int nj = 0; nj < 8; nj++)
#pragma unroll
            for (int r = 0; r < 4; r++) acc[mi][nj][r] = 0;

    const int lrow = tid >> 2, lchunk = tid & 3;
    const int8_t* gA = A + (size_t)(m0 + lrow) * K + lchunk * 16;
    const int8_t* gB = B + (size_t)(n0 + lrow) * K + lchunk * 16;
    const uint32_t sAb = smem_u32(sA), sBb = smem_u32(sB);
    const uint32_t dR0 = lrow * 64        + ((lchunk * 16) ^ ((( lrow       >> 1) & 3) << 4));
    const uint32_t dR1 = (lrow + 64) * 64 + ((lchunk * 16) ^ ((((lrow + 64) >> 1) & 3) << 4));

    // ldmatrix per-lane addresses (stage 0)
    uint32_t aAd[2][2], aBd[4][2];
    {
        int rb = wm * 32 + ((lane >> 3) & 1) * 8 + (lane & 7);
        int cb = (lane >> 4) * 16;
#pragma unroll
        for (int mi = 0; mi < 2; mi++) {
            int r = rb + mi * 16;
#pragma unroll
            for (int ks = 0; ks < 2; ks++) {
                int bc_ = ks * 32 + cb;
                aAd[mi][ks] = sAb + r * 64 + (bc_ ^ (((r >> 1) & 3) << 4));
            }
        }
        int rbB = wn * 64 + ((lane >> 4) & 1) * 8 + (lane & 7);
        int cbB = ((lane >> 3) & 1) * 16;
#pragma unroll
        for (int p = 0; p < 4; p++) {
            int r = rbB + p * 16;
#pragma unroll
            for (int ks = 0; ks < 2; ks++) {
                int bc_ = ks * 32 + cbB;
                aBd[p][ks] = sBb + r * 64 + (bc_ ^ (((r >> 1) & 3) << 4));
            }
        }
    }

    const int KT = K >> 6;
    const size_t rs64 = (size_t)64 * K;

    cp16(sAb + dR0, gA);          cp16(sAb + dR1, gA + rs64);
    cp16(sBb + dR0, gB);          cp16(sBb + dR1, gB + rs64);
    asm volatile("cp.async.commit_group;\n");

    for (int kt = 0; kt < KT; kt++) {
        if (kt + 1 < KT) {
            const uint32_t so = ((kt + 1) & 1) * (128 * 64);
            const int8_t* pA = gA + (kt + 1) * 64;
            const int8_t* pB = gB + (kt + 1) * 64;
            cp16(sAb + so + dR0, pA);          cp16(sAb + so + dR1, pA + rs64);
            cp16(sBb + so + dR0, pB);          cp16(sBb + so + dR1, pB + rs64);
        }
        asm volatile("cp.async.commit_group;\n");
        if (kt + 1 < KT) asm volatile("cp.async.wait_group 1;\n");
        else             asm volatile("cp.async.wait_group 0;\n");
        __syncthreads();

        const uint32_t so = (kt & 1) * 8192;
#pragma unroll
        for (int ks = 0; ks < 2; ks++) {
            int a0[4], a1[4];
            ldsm4(aAd[0][ks] + so, a0);
            ldsm4(aAd[1][ks] + so, a1);
#pragma unroll
            for (int p = 0; p < 4; p++) {
                int bf[4];
                ldsm4(aBd[p][ks] + so, bf);
                mma_s8(acc[0][2 * p],     a0, bf[0], bf[1]);
                mma_s8(acc[1][2 * p],     a1, bf[0], bf[1]);
                mma_s8(acc[0][2 * p + 1], a0, bf[2], bf[3]);
                mma_s8(acc[1][2 * p + 1], a1, bf[2], bf[3]);
            }
        }
        __syncthreads();
    }

    const float sa = __fdiv_rn(fmaxf(amaxA[0], 1e-8f), 127.0f);
    const float sb = __fdiv_rn(fmaxf(amaxB[0], 1e-8f), 127.0f);
    const float sc = sa * sb;
    float lmax = 0.0f;
#pragma unroll
    for (int mi = 0; mi < 2; mi++) {
        const int rowb = m0 + wm * 32 + mi * 16 + gid;
#pragma unroll
        for (int nj = 0; nj < 8; nj++) {
            const int col = n0 + wn * 64 + nj * 8 + 2 * tig;
            const float bi0 = bias[col], bi1 = bias[col + 1];
#pragma unroll
            for (int half = 0; half < 2; half++) {
                const int row = rowb + half * 8;
                const size_t off = (size_t)row * N + col;
                float v0 = (float)acc[mi][nj][half * 2]     * sc + bi0;
                float v1 = (float)acc[mi][nj][half * 2 + 1] * sc + bi1;
                if (EPI == 1) {
                    float2 rv = *reinterpret_cast<const float2*>(&res[off]);
                    v0 += rv.x; v1 += rv.y;
                }
                if (EPI == 2) {
                    v0 = 0.5f * v0 * (1.0f + erff(v0 * 0.70710678118654752440f));
                    v1 = 0.5f * v1 * (1.0f + erff(v1 * 0.70710678118654752440f));
                    lmax = fmaxf(lmax, fmaxf(fabsf(v0), fabsf(v1)));
                }
                *reinterpret_cast<float2*>(&C[off]) = make_float2(v0, v1);
            }
        }
    }
    if (EPI == 2) {
#pragma unroll
        for (int o = 16; o > 0; o >>= 1)
            lmax = fmaxf(lmax, __shfl_xor_sync(0xffffffffu, lmax, o));
        float* sred = reinterpret_cast<float*>(sA);
        if (lane == 0) sred[warp] = lmax;
        __syncthreads();
        if (tid == 0) {
            float t = sred[0];
#pragma unroll
            for (int k = 1; k < 8; k++) t = fmaxf(t, sred[k]);
            atomicMaxF(gmax, t);
        }
    }
}

// ---------------- temporal attention: one block per (b, c, h) ----------------
__global__ __launch_bounds__(256) void attn_k(const float* __restrict__ qkv,
                                              float* __restrict__ o,
                                              float* __restrict__ slot) {
    __shared__ float sQ[64][64];   // Q, later reused for V
    __shared__ float sKt[64][64];  // K transposed + rotated: [d][(t+d)&63]
    __shared__ float sS[64][64];   // scores rotated: [t][(s+t)&63]
    int id = blockIdx.x, tid = threadIdx.x;
    int h = id % 12, c = (id / 12) & 63, b = id / (12 * 64);
    size_t base = ((size_t)(b * 4096 + c * 64)) * DQKV + h * 64;

    for (int i = tid; i < 1024; i += 256) {
        int t = i >> 4, c4 = (i & 15) * 4;
        float4 q4 = *reinterpret_cast<const float4*>(&qkv[base + (size_t)t * DQKV + c4]);
        *reinterpret_cast<float4*>(&sQ[t][c4]) = q4;
        float4 k4 = *reinterpret_cast<const float4*>(&qkv[base + (size_t)t * DQKV + 768 + c4]);
        sKt[c4 + 0][(t + c4 + 0) & 63] = k4.x;
        sKt[c4 + 1][(t + c4 + 1) & 63] = k4.y;
        sKt[c4 + 2][(t + c4 + 2) & 63] = k4.z;
        sKt[c4 + 3][(t + c4 + 3) & 63] = k4.w;
    }
    __syncthreads();

    int i4 = tid >> 4, j4 = tid & 15;
    {
        float acc[4][4];
#pragma unroll
        for (int i = 0; i < 4; i++)
#pragma unroll
            for (int j = 0; j < 4; j++) acc[i][j] = 0.0f;
#pragma unroll 4
        for (int d = 0; d < 64; d++) {
            float qa[4], kb[4];
#pragma unroll
            for (int i = 0; i < 4; i++) qa[i] = sQ[i4 * 4 + i][d];
#pragma unroll
            for (int j = 0; j < 4; j++) kb[j] = sKt[d][((j4 * 4 + j) + d) & 63];
#pragma unroll
            for (int i = 0; i < 4; i++)
#pragma unroll
                for (int j = 0; j < 4; j++) acc[i][j] = fmaf(qa[i], kb[j], acc[i][j]);
        }
#pragma unroll
        for (int i = 0; i < 4; i++) {
            int tt = i4 * 4 + i;
#pragma unroll
            for (int j = 0; j < 4; j++) {
                int ss = j4 * 4 + j;
                sS[tt][(ss + tt) & 63] = acc[i][j] * 0.125f;
            }
        }
    }
    __syncthreads();

    for (int i = tid; i < 1024; i += 256) {
        int t = i >> 4, c4 = (i & 15) * 4;
        float4 v4 = *reinterpret_cast<const float4*>(&qkv[base + (size_t)t * DQKV + 1536 + c4]);
        *reinterpret_cast<float4*>(&sQ[t][c4]) = v4;
    }
    if (tid < 64) {
        int r = tid;
        float m = -3.402823466e38f;
        for (int s = 0; s < 64; s++) m = fmaxf(m, sS[r][(s + r) & 63]);
        float sum = 0.0f;
        for (int s = 0; s < 64; s++) {
            float e = expf(sS[r][(s + r) & 63] - m);
            sS[r][(s + r) & 63] = e;
            sum += e;
        }
        float inv = __fdiv_rn(1.0f, sum);
        for (int s = 0; s < 64; s++) sS[r][(s + r) & 63] *= inv;
    }
    __syncthreads();

    float acc[4][4];
#pragma unroll
    for (int i = 0; i < 4; i++)
#pragma unroll
        for (int j = 0; j < 4; j++) acc[i][j] = 0.0f;
#pragma unroll 4
    for (int s = 0; s < 64; s++) {
        float pa[4], vb[4];
#pragma unroll
        for (int i = 0; i < 4; i++) { int tt = i4 * 4 + i; pa[i] = sS[tt][(s + tt) & 63]; }
#pragma unroll
        for (int j = 0; j < 4; j++) vb[j] = sQ[s][j4 * 4 + j];
#pragma unroll
        for (int i = 0; i < 4; i++)
#pragma unroll
            for (int j = 0; j < 4; j++) acc[i][j] = fmaf(pa[i], vb[j], acc[i][j]);
    }
    float lmax = 0.0f;
#pragma unroll
    for (int i = 0; i < 4; i++) {
        int tt = i4 * 4 + i;
        size_t orow = ((size_t)(b * 4096 + c * 64 + tt)) * DM + h * 64;
#pragma unroll
        for (int j = 0; j < 4; j++) {
            int dd = j4 * 4 + j;
            o[orow + dd] = acc[i][j];
            lmax = fmaxf(lmax, fabsf(acc[i][j]));
        }
    }
#pragma unroll
    for (int off = 16; off > 0; off >>= 1)
        lmax = fmaxf(lmax, __shfl_xor_sync(0xffffffffu, lmax, off));
    if ((tid & 31) == 0) atomicMaxF(slot + (blockIdx.x & 31) * 64, lmax);
}

// ---------------- launch ----------------
extern "C" void kernel_launch(void* const* d_in, const int* in_sizes, int n_in,
                              void* d_out, int out_size) {
    const float* x      = (const float*)d_in[0];
    const float* ln1_g  = (const float*)d_in[1];
    const float* ln1_b  = (const float*)d_in[2];
    const float* qkv_w  = (const float*)d_in[3];
    const float* qkv_b  = (const float*)d_in[4];
    const float* proj_w = (const float*)d_in[5];
    const float* proj_b = (const float*)d_in[6];
    const float* ln2_g  = (const float*)d_in[7];
    const float* ln2_b  = (const float*)d_in[8];
    const float* fc1_w  = (const float*)d_in[9];
    const float* fc1_b  = (const float*)d_in[10];
    const float* fc2_w  = (const float*)d_in[11];
    const float* fc2_b  = (const float*)d_in[12];

    float *pf, *pqkv, *px2, *pfc1, *pamax, *pslots;
    int8_t *pq, *pfc1q, *pwqkv, *pwproj, *pwfc1, *pwfc2;
    cudaGetSymbolAddress((void**)&pf,    g_f);
    cudaGetSymbolAddress((void**)&pqkv,  g_qkv);
    cudaGetSymbolAddress((void**)&px2,   g_x2);
    cudaGetSymbolAddress((void**)&pfc1,  g_fc1);
    cudaGetSymbolAddress((void**)&pq,    g_q);
    cudaGetSymbolAddress((void**)&pfc1q, g_fc1q);
    cudaGetSymbolAddress((void**)&pwqkv, g_wqkv);
    cudaGetSymbolAddress((void**)&pwproj,g_wproj);
    cudaGetSymbolAddress((void**)&pwfc1, g_wfc1);
    cudaGetSymbolAddress((void**)&pwfc2, g_wfc2);
    cudaGetSymbolAddress((void**)&pamax, g_amax);
    cudaGetSymbolAddress((void**)&pslots,g_slots);

    zero_k<<<8, 256>>>(pamax, pslots);

    absmax_w_k<<<dim3(128, 4), 256>>>(qkv_w, proj_w, fc1_w, fc2_w, pamax);
    quant_w_k<<<dim3(128, 4), 256>>>(qkv_w, proj_w, fc1_w, fc2_w,
                                     pwqkv, pwproj, pwfc1, pwfc2, pamax);

    // attn branch
    ln_k<<<NTOK, 256>>>(x, ln1_g, ln1_b, pf, pslots + 0 * 2048);
    reduce_amax_k<<<1, 32>>>(pslots + 0 * 2048, pamax + 0);
    quant_a_k<<<2048, 256>>>(pf, pq, NTOK * DM / 4, pamax + 0);
    gemm_imma_k<0><<<dim3(DQKV / 128, NTOK / 128), 256>>>(
        pq, pwqkv, NTOK, DQKV, DM, pamax + 0, pamax + 4, qkv_b, nullptr, pqkv, nullptr);
    attn_k<<<8 * 64 * 12, 256>>>(pqkv, pf, pslots + 1 * 2048);
    reduce_amax_k<<<1, 32>>>(pslots + 1 * 2048, pamax + 1);
    quant_a_k<<<2048, 256>>>(pf, pq, NTOK * DM / 4, pamax + 1);
    gemm_imma_k<1><<<dim3(DM / 128, NTOK / 128), 256>>>(
        pq, pwproj, NTOK, DM, DM, pamax + 1, pamax + 5, proj_b, x, px2, nullptr);

    // mlp branch
    ln_k<<<NTOK, 256>>>(px2, ln2_g, ln2_b, pf, pslots + 2 * 2048);
    reduce_amax_k<<<1, 32>>>(pslots + 2 * 2048, pamax + 2);
    quant_a_k<<<2048, 256>>>(pf, pq, NTOK * DM / 4, pamax + 2);
    gemm_imma_k<2><<<dim3(DFC / 128, NTOK / 128), 256>>>(
        pq, pwfc1, NTOK, DFC, DM, pamax + 2, pamax + 6, fc1_b, nullptr, pfc1, pamax + 3);
    quant_a_k<<<4096, 256>>>(pfc1, pfc1q, NTOK * DFC / 4, pamax + 3);
    gemm_imma_k<1><<<dim3(DM / 128, NTOK / 128), 256>>>(
        pfc1q, pwfc2, NTOK, DM, DFC, pamax + 3, pamax + 7, fc2_b, px2, (float*)d_out, nullptr);
}

// round 6
// speedup vs baseline: 1.5554x; 1.5554x over previous
#include <cuda_runtime.h>
#include <cuda_bf16.h>
#include <cstdint>
#include <math.h>

#define NTOK 32768          // B * C * T = 8 * 64 * 64
#define DM   768
#define DQKV 2304
#define DFC  3072

// ---------------- scratch (device globals; no allocations) ----------------
__device__ __align__(16) float  g_f[(size_t)NTOK * DM];
__device__ __align__(16) float  g_qkv[(size_t)NTOK * DQKV];
__device__ __align__(16) float  g_x2[(size_t)NTOK * DM];
__device__ __align__(16) float  g_fc1[(size_t)NTOK * DFC];
__device__ __align__(16) __nv_bfloat16 g_qb[(size_t)NTOK * DM];     // quantized act as bf16
__device__ __align__(16) __nv_bfloat16 g_fc1q[(size_t)NTOK * DFC];
__device__ __align__(16) __nv_bfloat16 g_wqkv[DQKV * DM];
__device__ __align__(16) __nv_bfloat16 g_wproj[DM * DM];
__device__ __align__(16) __nv_bfloat16 g_wfc1[DFC * DM];
__device__ __align__(16) __nv_bfloat16 g_wfc2[DM * DFC];
__device__ __align__(16) float  g_amax[16];        // 0 ln1 1 attn 2 ln2 3 gelu 4..7 weights
__device__ __align__(16) float  g_slots[4 * 2048]; // spread amax slots (32 used, stride 64)

__device__ __forceinline__ void atomicMaxF(float* a, float v) {
    atomicMax(reinterpret_cast<unsigned int*>(a), __float_as_uint(v)); // v >= 0
}
__device__ __forceinline__ uint32_t smem_u32(const void* p) {
    return (uint32_t)__cvta_generic_to_shared(p);
}
__device__ __forceinline__ void cp16(uint32_t dst, const void* src) {
    asm volatile("cp.async.cg.shared.global [%0], [%1], 16;\n" :: "r"(dst), "l"(src));
}
__device__ __forceinline__ void ldsm4(uint32_t a, int* r) {
    asm volatile("ldmatrix.sync.aligned.m8n8.x4.shared.b16 {%0,%1,%2,%3}, [%4];"
                 : "=r"(r[0]), "=r"(r[1]), "=r"(r[2]), "=r"(r[3]) : "r"(a));
}
__device__ __forceinline__ void mma_bf16(float* c, const int* a, int b0, int b1) {
    asm volatile(
        "mma.sync.aligned.m16n8k16.row.col.f32.bf16.bf16.f32 "
        "{%0,%1,%2,%3}, {%4,%5,%6,%7}, {%8,%9}, {%0,%1,%2,%3};\n"
        : "+f"(c[0]), "+f"(c[1]), "+f"(c[2]), "+f"(c[3])
        : "r"(a[0]), "r"(a[1]), "r"(a[2]), "r"(a[3]), "r"(b0), "r"(b1));
}

// quantize two floats -> packed bf16x2 (values are small ints, conversion exact)
__device__ __forceinline__ uint32_t q2bf(float a, float b, float s) {
    float ra = fminf(fmaxf(rintf(__fdiv_rn(a, s)), -128.0f), 127.0f);
    float rb = fminf(fmaxf(rintf(__fdiv_rn(b, s)), -128.0f), 127.0f);
    uint32_t r;
    asm("cvt.rn.bf16x2.f32 %0, %1, %2;" : "=r"(r) : "f"(rb), "f"(ra)); // hi=rb, lo=ra
    return r;
}

// ---------------- init / reduce ----------------
__global__ void zero_k(float* amax, float* slots) {
    int i = blockIdx.x * blockDim.x + threadIdx.x;
    if (i < 16) amax[i] = 0.0f;
    for (int j = i; j < 4 * 2048; j += gridDim.x * blockDim.x) slots[j] = 0.0f;
}

__global__ void reduce_amax_k(const float* __restrict__ slots, float* __restrict__ dst) {
    float v = slots[threadIdx.x * 64];
#pragma unroll
    for (int o = 16; o > 0; o >>= 1) v = fmaxf(v, __shfl_xor_sync(0xffffffffu, v, o));
    if (threadIdx.x == 0) dst[0] = v;
}

// ---------------- weight absmax (segmented, float4) ----------------
__global__ __launch_bounds__(256) void absmax_w_k(
    const float* __restrict__ w0, const float* __restrict__ w1,
    const float* __restrict__ w2, const float* __restrict__ w3, float* __restrict__ amax)
{
    const float* w; int n4;
    switch (blockIdx.y) {
        case 0: w = w0; n4 = DQKV * DM / 4; break;
        case 1: w = w1; n4 = DM * DM / 4;   break;
        case 2: w = w2; n4 = DFC * DM / 4;  break;
        default: w = w3; n4 = DM * DFC / 4; break;
    }
    float m = 0.0f;
#pragma unroll 4
    for (int i = blockIdx.x * 256 + threadIdx.x; i < n4; i += gridDim.x * 256) {
        float4 v = reinterpret_cast<const float4*>(w)[i];
        m = fmaxf(m, fmaxf(fmaxf(fabsf(v.x), fabsf(v.y)), fmaxf(fabsf(v.z), fabsf(v.w))));
    }
#pragma unroll
    for (int o = 16; o > 0; o >>= 1) m = fmaxf(m, __shfl_xor_sync(0xffffffffu, m, o));
    __shared__ float sm[8];
    if ((threadIdx.x & 31) == 0) sm[threadIdx.x >> 5] = m;
    __syncthreads();
    if (threadIdx.x == 0) {
        float t = sm[0];
#pragma unroll
        for (int k = 1; k < 8; k++) t = fmaxf(t, sm[k]);
        atomicMaxF(&amax[4 + blockIdx.y], t);
    }
}

// ---------------- weight quantize (segmented, float4 -> 2x bf16x2) ----------------
__global__ __launch_bounds__(256) void quant_w_k(
    const float* __restrict__ w0, const float* __restrict__ w1,
    const float* __restrict__ w2, const float* __restrict__ w3,
    __nv_bfloat16* __restrict__ q0, __nv_bfloat16* __restrict__ q1,
    __nv_bfloat16* __restrict__ q2, __nv_bfloat16* __restrict__ q3,
    const float* __restrict__ amax)
{
    const float* w; __nv_bfloat16* q; int n4;
    switch (blockIdx.y) {
        case 0: w = w0; q = q0; n4 = DQKV * DM / 4; break;
        case 1: w = w1; q = q1; n4 = DM * DM / 4;   break;
        case 2: w = w2; q = q2; n4 = DFC * DM / 4;  break;
        default: w = w3; q = q3; n4 = DM * DFC / 4; break;
    }
    float s = __fdiv_rn(fmaxf(amax[4 + blockIdx.y], 1e-8f), 127.0f);
#pragma unroll 4
    for (int i = blockIdx.x * 256 + threadIdx.x; i < n4; i += gridDim.x * 256) {
        float4 v = reinterpret_cast<const float4*>(w)[i];
        uint2 p;
        p.x = q2bf(v.x, v.y, s);
        p.y = q2bf(v.z, v.w, s);
        reinterpret_cast<uint2*>(q)[i] = p;
    }
}

// ---------------- activation quantize (float4 -> 2x bf16x2) ----------------
__global__ __launch_bounds__(256) void quant_a_k(const float* __restrict__ x,
                                                 __nv_bfloat16* __restrict__ q, int n4,
                                                 const float* __restrict__ amax) {
    float s = __fdiv_rn(fmaxf(amax[0], 1e-8f), 127.0f);
#pragma unroll 4
    for (int i = blockIdx.x * 256 + threadIdx.x; i < n4; i += gridDim.x * 256) {
        float4 v = reinterpret_cast<const float4*>(x)[i];
        uint2 p;
        p.x = q2bf(v.x, v.y, s);
        p.y = q2bf(v.z, v.w, s);
        reinterpret_cast<uint2*>(q)[i] = p;
    }
}

// ---------------- layernorm + fused absmax (warp-shuffle reductions) ----------------
__global__ __launch_bounds__(256) void ln_k(const float* __restrict__ x,
                                            const float* __restrict__ g,
                                            const float* __restrict__ b,
                                            float* __restrict__ out,
                                            float* __restrict__ slot) {
    __shared__ float sm[8];
    __shared__ float bc[2];
    int row = blockIdx.x, tid = threadIdx.x;
    int lane = tid & 31, wid = tid >> 5;
    const float* xr = x + (size_t)row * DM;
    float v0 = xr[tid], v1 = xr[tid + 256], v2 = xr[tid + 512];

    float s = v0 + v1 + v2;
#pragma unroll
    for (int o = 16; o > 0; o >>= 1) s += __shfl_xor_sync(0xffffffffu, s, o);
    if (lane == 0) sm[wid] = s;
    __syncthreads();
    if (wid == 0) {
        float t = (lane < 8) ? sm[lane] : 0.0f;
#pragma unroll
        for (int o = 4; o > 0; o >>= 1) t += __shfl_xor_sync(0xffffffffu, t, o);
        if (lane == 0) bc[0] = t * (1.0f / 768.0f);
    }
    __syncthreads();
    float mean = bc[0];
    float d0 = v0 - mean, d1 = v1 - mean, d2 = v2 - mean;
    float ss = d0 * d0 + d1 * d1 + d2 * d2;
#pragma unroll
    for (int o = 16; o > 0; o >>= 1) ss += __shfl_xor_sync(0xffffffffu, ss, o);
    if (lane == 0) sm[wid] = ss;
    __syncthreads();
    if (wid == 0) {
        float t = (lane < 8) ? sm[lane] : 0.0f;
#pragma unroll
        for (int o = 4; o > 0; o >>= 1) t += __shfl_xor_sync(0xffffffffu, t, o);
        if (lane == 0) bc[1] = __frsqrt_rn(t * (1.0f / 768.0f) + 1e-5f);
    }
    __syncthreads();
    float rs = bc[1];
    float o0 = d0 * rs * g[tid]       + b[tid];
    float o1 = d1 * rs * g[tid + 256] + b[tid + 256];
    float o2 = d2 * rs * g[tid + 512] + b[tid + 512];
    float* orow = out + (size_t)row * DM;
    orow[tid] = o0; orow[tid + 256] = o1; orow[tid + 512] = o2;

    float lm = fmaxf(fmaxf(fabsf(o0), fabsf(o1)), fabsf(o2));
#pragma unroll
    for (int o = 16; o > 0; o >>= 1) lm = fmaxf(lm, __shfl_xor_sync(0xffffffffu, lm, o));
    if (lane == 0) sm[wid] = lm;
    __syncthreads();
    if (tid == 0) {
        float t = sm[0];
#pragma unroll
        for (int k = 1; k < 8; k++) t = fmaxf(t, sm[k]);
        atomicMaxF(slot + (row & 31) * 64, t);
    }
}

// ---------------- bf16 HMMA GEMM, C = A[M,K] * B[N,K]^T ----------------
// Block 128x128, BK=64 (128B rows, XOR swizzle on 16B chunks), 2-stage cp.async.
// Warp grid 4(M) x 2(N); warp tile 32x64 via mma.m16n8k16.bf16 (fp32 accum).
// EPI: 0 = bias, 1 = bias + residual, 2 = bias + exact GELU + fused absmax
template<int EPI>
__global__ __launch_bounds__(256) void gemm_bf16_k(
    const __nv_bfloat16* __restrict__ A, const __nv_bfloat16* __restrict__ B,
    int M, int N, int K,
    const float* __restrict__ amaxA, const float* __restrict__ amaxB,
    const float* __restrict__ bias, const float* __restrict__ res,
    float* __restrict__ C, float* __restrict__ gmax)
{
    extern __shared__ __align__(1024) char smem[];   // 2 stages x (A 16KB + B 16KB)
    const uint32_t sbase = smem_u32(smem);
    const int tid  = threadIdx.x;
    const int lane = tid & 31, warp = tid >> 5;
    const int wm = warp & 3, wn = warp >> 2;
    const int m0 = blockIdx.y * 128, n0 = blockIdx.x * 128;
    const int gid = lane >> 2, tig = lane & 3;

    float acc[2][8][4];
#pragma unroll
    for (int mi = 0; mi < 2; mi++)
#pragma unroll
        for (int nj = 0; nj < 8; nj++)
#pragma unroll
            for (int r = 0; r < 4; r++) acc[mi][nj][r] = 0.0f;

    // global->smem mapping: thread t handles row t>>1, chunks (t&1)*4 .. +3 (16B each)
    const int lrow = tid >> 1, lcb = (tid & 1) * 4;
    const char* gA = (const char*)(A + (size_t)(m0 + lrow) * K) + lcb * 16;
    const char* gB = (const char*)(B + (size_t)(n0 + lrow) * K) + lcb * 16;
    uint32_t dst[4];
#pragma unroll
    for (int c = 0; c < 4; c++)
        dst[c] = lrow * 128 + (((lcb + c) ^ (lrow & 7)) << 4);

    // ldmatrix lane addressing (row-dependent swizzle s = row & 7 = lane & 7)
    const int s7 = lane & 7;
    uint32_t koff[4];
#pragma unroll
    for (int ks = 0; ks < 4; ks++) koff[ks] = ((ks * 2) ^ (s7 & 6)) << 4;
    const int rowA0 = wm * 32 + s7 + ((lane >> 3) & 1) * 8;
    const uint32_t aAb = rowA0 * 128 + (((((lane >> 4) & 1)) ^ (s7 & 1)) << 4);
    const int rowB0 = wn * 64 + s7 + ((lane >> 4) & 1) * 8;
    const uint32_t aBb = 16384 + rowB0 * 128 + (((((lane >> 3) & 1)) ^ (s7 & 1)) << 4);

    const int KT = K >> 6;

    // prologue: tile 0 -> stage 0
#pragma unroll
    for (int c = 0; c < 4; c++) {
        cp16(sbase + dst[c], gA + c * 16);
        cp16(sbase + 16384 + dst[c], gB + c * 16);
    }
    asm volatile("cp.async.commit_group;\n");

    for (int kt = 0; kt < KT; kt++) {
        if (kt + 1 < KT) {
            const uint32_t so = ((kt + 1) & 1) * 32768;
            const char* pA = gA + (size_t)(kt + 1) * 128;
            const char* pB = gB + (size_t)(kt + 1) * 128;
#pragma unroll
            for (int c = 0; c < 4; c++) {
                cp16(sbase + so + dst[c], pA + c * 16);
                cp16(sbase + so + 16384 + dst[c], pB + c * 16);
            }
            asm volatile("cp.async.commit_group;\n");
            asm volatile("cp.async.wait_group 1;\n");
        } else {
            asm volatile("cp.async.wait_group 0;\n");
        }
        __syncthreads();

        const uint32_t so = (kt & 1) * 32768;
#pragma unroll
        for (int ks = 0; ks < 4; ks++) {
            int a0[4], a1[4];
            ldsm4(sbase + so + aAb + koff[ks], a0);
            ldsm4(sbase + so + aAb + 2048 + koff[ks], a1);
#pragma unroll
            for (int p = 0; p < 4; p++) {
                int bf[4];
                ldsm4(sbase + so + aBb + p * 2048 + koff[ks], bf);
                mma_bf16(acc[0][2 * p],     a0, bf[0], bf[1]);
                mma_bf16(acc[1][2 * p],     a1, bf[0], bf[1]);
                mma_bf16(acc[0][2 * p + 1], a0, bf[2], bf[3]);
                mma_bf16(acc[1][2 * p + 1], a1, bf[2], bf[3]);
            }
        }
        __syncthreads();
    }

    // epilogue
    const float sa = __fdiv_rn(fmaxf(amaxA[0], 1e-8f), 127.0f);
    const float sb = __fdiv_rn(fmaxf(amaxB[0], 1e-8f), 127.0f);
    const float sc = sa * sb;
    float lmax = 0.0f;
#pragma unroll
    for (int mi = 0; mi < 2; mi++) {
        const int rowb = m0 + wm * 32 + mi * 16 + gid;
#pragma unroll
        for (int nj = 0; nj < 8; nj++) {
            const int col = n0 + wn * 64 + nj * 8 + 2 * tig;
            const float bi0 = bias[col], bi1 = bias[col + 1];
#pragma unroll
            for (int half = 0; half < 2; half++) {
                const int row = rowb + half * 8;
                const size_t off = (size_t)row * N + col;
                float v0 = acc[mi][nj][half * 2]     * sc + bi0;
                float v1 = acc[mi][nj][half * 2 + 1] * sc + bi1;
                if (EPI == 1) {
                    float2 rv = *reinterpret_cast<const float2*>(&res[off]);
                    v0 += rv.x; v1 += rv.y;
                }
                if (EPI == 2) {
                    v0 = 0.5f * v0 * (1.0f + erff(v0 * 0.70710678118654752440f));
                    v1 = 0.5f * v1 * (1.0f + erff(v1 * 0.70710678118654752440f));
                    lmax = fmaxf(lmax, fmaxf(fabsf(v0), fabsf(v1)));
                }
                *reinterpret_cast<float2*>(&C[off]) = make_float2(v0, v1);
            }
        }
    }
    if (EPI == 2) {
#pragma unroll
        for (int o = 16; o > 0; o >>= 1)
            lmax = fmaxf(lmax, __shfl_xor_sync(0xffffffffu, lmax, o));
        __shared__ float sred[8];
        if (lane == 0) sred[warp] = lmax;
        __syncthreads();
        if (tid == 0) {
            float t = sred[0];
#pragma unroll
            for (int k = 1; k < 8; k++) t = fmaxf(t, sred[k]);
            atomicMaxF(gmax + ((blockIdx.y * gridDim.x + blockIdx.x) & 31) * 64, t);
        }
    }
}

// ---------------- temporal attention: one block per (b, c, h) ----------------
__global__ __launch_bounds__(256) void attn_k(const float* __restrict__ qkv,
                                              float* __restrict__ o,
                                              float* __restrict__ slot) {
    __shared__ float sQ[64][64];   // Q, later reused for V
    __shared__ float sKt[64][64];  // K transposed + rotated: [d][(t+d)&63]
    __shared__ float sS[64][64];   // scores rotated: [t][(s+t)&63]
    int id = blockIdx.x, tid = threadIdx.x;
    int h = id % 12, c = (id / 12) & 63, b = id / (12 * 64);
    size_t base = ((size_t)(b * 4096 + c * 64)) * DQKV + h * 64;

    for (int i = tid; i < 1024; i += 256) {
        int t = i >> 4, c4 = (i & 15) * 4;
        float4 q4 = *reinterpret_cast<const float4*>(&qkv[base + (size_t)t * DQKV + c4]);
        *reinterpret_cast<float4*>(&sQ[t][c4]) = q4;
        float4 k4 = *reinterpret_cast<const float4*>(&qkv[base + (size_t)t * DQKV + 768 + c4]);
        sKt[c4 + 0][(t + c4 + 0) & 63] = k4.x;
        sKt[c4 + 1][(t + c4 + 1) & 63] = k4.y;
        sKt[c4 + 2][(t + c4 + 2) & 63] = k4.z;
        sKt[c4 + 3][(t + c4 + 3) & 63] = k4.w;
    }
    __syncthreads();

    int i4 = tid >> 4, j4 = tid & 15;
    {
        float acc[4][4];
#pragma unroll
        for (int i = 0; i < 4; i++)
#pragma unroll
            for (int j = 0; j < 4; j++) acc[i][j] = 0.0f;
#pragma unroll 4
        for (int d = 0; d < 64; d++) {
            float qa[4], kb[4];
#pragma unroll
            for (int i = 0; i < 4; i++) qa[i] = sQ[i4 * 4 + i][d];
#pragma unroll
            for (int j = 0; j < 4; j++) kb[j] = sKt[d][((j4 * 4 + j) + d) & 63];
#pragma unroll
            for (int i = 0; i < 4; i++)
#pragma unroll
                for (int j = 0; j < 4; j++) acc[i][j] = fmaf(qa[i], kb[j], acc[i][j]);
        }
#pragma unroll
        for (int i = 0; i < 4; i++) {
            int tt = i4 * 4 + i;
#pragma unroll
            for (int j = 0; j < 4; j++) {
                int ss = j4 * 4 + j;
                sS[tt][(ss + tt) & 63] = acc[i][j] * 0.125f;
            }
        }
    }
    __syncthreads();

    for (int i = tid; i < 1024; i += 256) {
        int t = i >> 4, c4 = (i & 15) * 4;
        float4 v4 = *reinterpret_cast<const float4*>(&qkv[base + (size_t)t * DQKV + 1536 + c4]);
        *reinterpret_cast<float4*>(&sQ[t][c4]) = v4;
    }
    if (tid < 64) {
        int r = tid;
        float m = -3.402823466e38f;
        for (int s = 0; s < 64; s++) m = fmaxf(m, sS[r][(s + r) & 63]);
        float sum = 0.0f;
        for (int s = 0; s < 64; s++) {
            float e = expf(sS[r][(s + r) & 63] - m);
            sS[r][(s + r) & 63] = e;
            sum += e;
        }
        float inv = __fdiv_rn(1.0f, sum);
        for (int s = 0; s < 64; s++) sS[r][(s + r) & 63] *= inv;
    }
    __syncthreads();

    float acc[4][4];
#pragma unroll
    for (int i = 0; i < 4; i++)
#pragma unroll
        for (int j = 0; j < 4; j++) acc[i][j] = 0.0f;
#pragma unroll 4
    for (int s = 0; s < 64; s++) {
        float pa[4], vb[4];
#pragma unroll
        for (int i = 0; i < 4; i++) { int tt = i4 * 4 + i; pa[i] = sS[tt][(s + tt) & 63]; }
#pragma unroll
        for (int j = 0; j < 4; j++) vb[j] = sQ[s][j4 * 4 + j];
#pragma unroll
        for (int i = 0; i < 4; i++)
#pragma unroll
            for (int j = 0; j < 4; j++) acc[i][j] = fmaf(pa[i], vb[j], acc[i][j]);
    }
    float lmax = 0.0f;
#pragma unroll
    for (int i = 0; i < 4; i++) {
        int tt = i4 * 4 + i;
        size_t orow = ((size_t)(b * 4096 + c * 64 + tt)) * DM + h * 64;
#pragma unroll
        for (int j = 0; j < 4; j++) {
            int dd = j4 * 4 + j;
            o[orow + dd] = acc[i][j];
            lmax = fmaxf(lmax, fabsf(acc[i][j]));
        }
    }
#pragma unroll
    for (int off = 16; off > 0; off >>= 1)
        lmax = fmaxf(lmax, __shfl_xor_sync(0xffffffffu, lmax, off));
    if ((tid & 31) == 0) atomicMaxF(slot + (blockIdx.x & 31) * 64, lmax);
}

// ---------------- launch ----------------
extern "C" void kernel_launch(void* const* d_in, const int* in_sizes, int n_in,
                              void* d_out, int out_size) {
    const float* x      = (const float*)d_in[0];
    const float* ln1_g  = (const float*)d_in[1];
    const float* ln1_b  = (const float*)d_in[2];
    const float* qkv_w  = (const float*)d_in[3];
    const float* qkv_b  = (const float*)d_in[4];
    const float* proj_w = (const float*)d_in[5];
    const float* proj_b = (const float*)d_in[6];
    const float* ln2_g  = (const float*)d_in[7];
    const float* ln2_b  = (const float*)d_in[8];
    const float* fc1_w  = (const float*)d_in[9];
    const float* fc1_b  = (const float*)d_in[10];
    const float* fc2_w  = (const float*)d_in[11];
    const float* fc2_b  = (const float*)d_in[12];

    float *pf, *pqkv, *px2, *pfc1, *pamax, *pslots;
    __nv_bfloat16 *pq, *pfc1q, *pwqkv, *pwproj, *pwfc1, *pwfc2;
    cudaGetSymbolAddress((void**)&pf,    g_f);
    cudaGetSymbolAddress((void**)&pqkv,  g_qkv);
    cudaGetSymbolAddress((void**)&px2,   g_x2);
    cudaGetSymbolAddress((void**)&pfc1,  g_fc1);
    cudaGetSymbolAddress((void**)&pq,    g_qb);
    cudaGetSymbolAddress((void**)&pfc1q, g_fc1q);
    cudaGetSymbolAddress((void**)&pwqkv, g_wqkv);
    cudaGetSymbolAddress((void**)&pwproj,g_wproj);
    cudaGetSymbolAddress((void**)&pwfc1, g_wfc1);
    cudaGetSymbolAddress((void**)&pwfc2, g_wfc2);
    cudaGetSymbolAddress((void**)&pamax, g_amax);
    cudaGetSymbolAddress((void**)&pslots,g_slots);

    const int SMEM = 65536;   // 2 stages x 32KB
    cudaFuncSetAttribute(gemm_bf16_k<0>, cudaFuncAttributeMaxDynamicSharedMemorySize, SMEM);
    cudaFuncSetAttribute(gemm_bf16_k<1>, cudaFuncAttributeMaxDynamicSharedMemorySize, SMEM);
    cudaFuncSetAttribute(gemm_bf16_k<2>, cudaFuncAttributeMaxDynamicSharedMemorySize, SMEM);

    zero_k<<<8, 256>>>(pamax, pslots);

    absmax_w_k<<<dim3(128, 4), 256>>>(qkv_w, proj_w, fc1_w, fc2_w, pamax);
    quant_w_k<<<dim3(128, 4), 256>>>(qkv_w, proj_w, fc1_w, fc2_w,
                                     pwqkv, pwproj, pwfc1, pwfc2, pamax);

    // attn branch
    ln_k<<<NTOK, 256>>>(x, ln1_g, ln1_b, pf, pslots + 0 * 2048);
    reduce_amax_k<<<1, 32>>>(pslots + 0 * 2048, pamax + 0);
    quant_a_k<<<2048, 256>>>(pf, pq, NTOK * DM / 4, pamax + 0);
    gemm_bf16_k<0><<<dim3(DQKV / 128, NTOK / 128), 256, SMEM>>>(
        pq, pwqkv, NTOK, DQKV, DM, pamax + 0, pamax + 4, qkv_b, nullptr, pqkv, nullptr);
    attn_k<<<8 * 64 * 12, 256>>>(pqkv, pf, pslots + 1 * 2048);
    reduce_amax_k<<<1, 32>>>(pslots + 1 * 2048, pamax + 1);
    quant_a_k<<<2048, 256>>>(pf, pq, NTOK * DM / 4, pamax + 1);
    gemm_bf16_k<1><<<dim3(DM / 128, NTOK / 128), 256, SMEM>>>(
        pq, pwproj, NTOK, DM, DM, pamax + 1, pamax + 5, proj_b, x, px2, nullptr);

    // mlp branch
    ln_k<<<NTOK, 256>>>(px2, ln2_g, ln2_b, pf, pslots + 2 * 2048);
    reduce_amax_k<<<1, 32>>>(pslots + 2 * 2048, pamax + 2);
    quant_a_k<<<2048, 256>>>(pf, pq, NTOK * DM / 4, pamax + 2);
    gemm_bf16_k<2><<<dim3(DFC / 128, NTOK / 128), 256, SMEM>>>(
        pq, pwfc1, NTOK, DFC, DM, pamax + 2, pamax + 6, fc1_b, nullptr, pfc1,
        pslots + 3 * 2048);
    reduce_amax_k<<<1, 32>>>(pslots + 3 * 2048, pamax + 3);
    quant_a_k<<<4096, 256>>>(pfc1, pfc1q, NTOK * DFC / 4, pamax + 3);
    gemm_bf16_k<1><<<dim3(DM / 128, NTOK / 128), 256, SMEM>>>(
        pfc1q, pwfc2, NTOK, DM, DFC, pamax + 3, pamax + 7, fc2_b, px2, (float*)d_out, nullptr);
}

// round 7
// speedup vs baseline: 1.6548x; 1.0639x over previous
#include <cuda_runtime.h>
#include <cuda_bf16.h>
#include <cstdint>
#include <math.h>

#define NTOK 32768          // B * C * T = 8 * 64 * 64
#define DM   768
#define DQKV 2304
#define DFC  3072

// ---------------- scratch (device globals; no allocations) ----------------
__device__ __align__(16) float  g_f[(size_t)NTOK * DM];
__device__ __align__(16) float  g_qkv[(size_t)NTOK * DQKV];
__device__ __align__(16) float  g_x2[(size_t)NTOK * DM];
__device__ __align__(16) float  g_fc1[(size_t)NTOK * DFC];
__device__ __align__(16) __nv_bfloat16 g_qb[(size_t)NTOK * DM];     // quantized act as bf16
__device__ __align__(16) __nv_bfloat16 g_fc1q[(size_t)NTOK * DFC];
__device__ __align__(16) __nv_bfloat16 g_wqkv[DQKV * DM];
__device__ __align__(16) __nv_bfloat16 g_wproj[DM * DM];
__device__ __align__(16) __nv_bfloat16 g_wfc1[DFC * DM];
__device__ __align__(16) __nv_bfloat16 g_wfc2[DM * DFC];
__device__ __align__(16) float  g_amax[16];        // 4..7 weight amax
__device__ __align__(16) float  g_slots[4 * 2048]; // spread amax slots (32 used, stride 64)

__device__ __forceinline__ void atomicMaxF(float* a, float v) {
    atomicMax(reinterpret_cast<unsigned int*>(a), __float_as_uint(v)); // v >= 0
}
__device__ __forceinline__ uint32_t smem_u32(const void* p) {
    return (uint32_t)__cvta_generic_to_shared(p);
}
__device__ __forceinline__ void cp16(uint32_t dst, const void* src) {
    asm volatile("cp.async.cg.shared.global [%0], [%1], 16;\n" :: "r"(dst), "l"(src));
}
__device__ __forceinline__ void ldsm4(uint32_t a, int* r) {
    asm volatile("ldmatrix.sync.aligned.m8n8.x4.shared.b16 {%0,%1,%2,%3}, [%4];"
                 : "=r"(r[0]), "=r"(r[1]), "=r"(r[2]), "=r"(r[3]) : "r"(a));
}
__device__ __forceinline__ void mma_bf16(float* c, const int* a, int b0, int b1) {
    asm volatile(
        "mma.sync.aligned.m16n8k16.row.col.f32.bf16.bf16.f32 "
        "{%0,%1,%2,%3}, {%4,%5,%6,%7}, {%8,%9}, {%0,%1,%2,%3};\n"
        : "+f"(c[0]), "+f"(c[1]), "+f"(c[2]), "+f"(c[3])
        : "r"(a[0]), "r"(a[1]), "r"(a[2]), "r"(a[3]), "r"(b0), "r"(b1));
}

// max over n slot entries (stride 64 floats); n=1 for plain scalar
__device__ __forceinline__ float amax_get(const float* __restrict__ p, int n) {
    float m = p[0];
    for (int i = 1; i < n; i++) m = fmaxf(m, p[i * 64]);
    return fmaxf(m, 1e-8f);
}

// quantize two floats -> packed bf16x2 (values are small ints, conversion exact)
__device__ __forceinline__ uint32_t q2bf(float a, float b, float s) {
    float ra = fminf(fmaxf(rintf(__fdiv_rn(a, s)), -128.0f), 127.0f);
    float rb = fminf(fmaxf(rintf(__fdiv_rn(b, s)), -128.0f), 127.0f);
    uint32_t r;
    asm("cvt.rn.bf16x2.f32 %0, %1, %2;" : "=r"(r) : "f"(rb), "f"(ra)); // hi=rb, lo=ra
    return r;
}

// ---------------- init ----------------
__global__ void zero_k(float* amax, float* slots) {
    int i = blockIdx.x * blockDim.x + threadIdx.x;
    if (i < 16) amax[i] = 0.0f;
    for (int j = i; j < 4 * 2048; j += gridDim.x * blockDim.x) slots[j] = 0.0f;
}

// ---------------- weight absmax (segmented, float4) ----------------
__global__ __launch_bounds__(256) void absmax_w_k(
    const float* __restrict__ w0, const float* __restrict__ w1,
    const float* __restrict__ w2, const float* __restrict__ w3, float* __restrict__ amax)
{
    const float* w; int n4;
    switch (blockIdx.y) {
        case 0: w = w0; n4 = DQKV * DM / 4; break;
        case 1: w = w1; n4 = DM * DM / 4;   break;
        case 2: w = w2; n4 = DFC * DM / 4;  break;
        default: w = w3; n4 = DM * DFC / 4; break;
    }
    float m = 0.0f;
#pragma unroll 4
    for (int i = blockIdx.x * 256 + threadIdx.x; i < n4; i += gridDim.x * 256) {
        float4 v = reinterpret_cast<const float4*>(w)[i];
        m = fmaxf(m, fmaxf(fmaxf(fabsf(v.x), fabsf(v.y)), fmaxf(fabsf(v.z), fabsf(v.w))));
    }
#pragma unroll
    for (int o = 16; o > 0; o >>= 1) m = fmaxf(m, __shfl_xor_sync(0xffffffffu, m, o));
    __shared__ float sm[8];
    if ((threadIdx.x & 31) == 0) sm[threadIdx.x >> 5] = m;
    __syncthreads();
    if (threadIdx.x == 0) {
        float t = sm[0];
#pragma unroll
        for (int k = 1; k < 8; k++) t = fmaxf(t, sm[k]);
        atomicMaxF(&amax[4 + blockIdx.y], t);
    }
}

// ---------------- weight quantize (segmented, float4 -> 2x bf16x2) ----------------
__global__ __launch_bounds__(256) void quant_w_k(
    const float* __restrict__ w0, const float* __restrict__ w1,
    const float* __restrict__ w2, const float* __restrict__ w3,
    __nv_bfloat16* __restrict__ q0, __nv_bfloat16* __restrict__ q1,
    __nv_bfloat16* __restrict__ q2, __nv_bfloat16* __restrict__ q3,
    const float* __restrict__ amax)
{
    const float* w; __nv_bfloat16* q; int n4;
    switch (blockIdx.y) {
        case 0: w = w0; q = q0; n4 = DQKV * DM / 4; break;
        case 1: w = w1; q = q1; n4 = DM * DM / 4;   break;
        case 2: w = w2; q = q2; n4 = DFC * DM / 4;  break;
        default: w = w3; q = q3; n4 = DM * DFC / 4; break;
    }
    float s = __fdiv_rn(amax_get(&amax[4 + blockIdx.y], 1), 127.0f);
#pragma unroll 4
    for (int i = blockIdx.x * 256 + threadIdx.x; i < n4; i += gridDim.x * 256) {
        float4 v = reinterpret_cast<const float4*>(w)[i];
        uint2 p;
        p.x = q2bf(v.x, v.y, s);
        p.y = q2bf(v.z, v.w, s);
        reinterpret_cast<uint2*>(q)[i] = p;
    }
}

// ---------------- activation quantize (float4 -> 2x bf16x2, slot-reduced scale) ----
__global__ __launch_bounds__(256) void quant_a_k(const float* __restrict__ x,
                                                 __nv_bfloat16* __restrict__ q, int n4,
                                                 const float* __restrict__ slots) {
    float s = __fdiv_rn(amax_get(slots, 32), 127.0f);
#pragma unroll 4
    for (int i = blockIdx.x * 256 + threadIdx.x; i < n4; i += gridDim.x * 256) {
        float4 v = reinterpret_cast<const float4*>(x)[i];
        uint2 p;
        p.x = q2bf(v.x, v.y, s);
        p.y = q2bf(v.z, v.w, s);
        reinterpret_cast<uint2*>(q)[i] = p;
    }
}

// ---------------- layernorm + fused absmax (warp-shuffle reductions) ----------------
__global__ __launch_bounds__(256) void ln_k(const float* __restrict__ x,
                                            const float* __restrict__ g,
                                            const float* __restrict__ b,
                                            float* __restrict__ out,
                                            float* __restrict__ slot) {
    __shared__ float sm[8];
    __shared__ float bc[2];
    int row = blockIdx.x, tid = threadIdx.x;
    int lane = tid & 31, wid = tid >> 5;
    const float* xr = x + (size_t)row * DM;
    float v0 = xr[tid], v1 = xr[tid + 256], v2 = xr[tid + 512];

    float s = v0 + v1 + v2;
#pragma unroll
    for (int o = 16; o > 0; o >>= 1) s += __shfl_xor_sync(0xffffffffu, s, o);
    if (lane == 0) sm[wid] = s;
    __syncthreads();
    if (wid == 0) {
        float t = (lane < 8) ? sm[lane] : 0.0f;
#pragma unroll
        for (int o = 4; o > 0; o >>= 1) t += __shfl_xor_sync(0xffffffffu, t, o);
        if (lane == 0) bc[0] = t * (1.0f / 768.0f);
    }
    __syncthreads();
    float mean = bc[0];
    float d0 = v0 - mean, d1 = v1 - mean, d2 = v2 - mean;
    float ss = d0 * d0 + d1 * d1 + d2 * d2;
#pragma unroll
    for (int o = 16; o > 0; o >>= 1) ss += __shfl_xor_sync(0xffffffffu, ss, o);
    if (lane == 0) sm[wid] = ss;
    __syncthreads();
    if (wid == 0) {
        float t = (lane < 8) ? sm[lane] : 0.0f;
#pragma unroll
        for (int o = 4; o > 0; o >>= 1) t += __shfl_xor_sync(0xffffffffu, t, o);
        if (lane == 0) bc[1] = __frsqrt_rn(t * (1.0f / 768.0f) + 1e-5f);
    }
    __syncthreads();
    float rs = bc[1];
    float o0 = d0 * rs * g[tid]       + b[tid];
    float o1 = d1 * rs * g[tid + 256] + b[tid + 256];
    float o2 = d2 * rs * g[tid + 512] + b[tid + 512];
    float* orow = out + (size_t)row * DM;
    orow[tid] = o0; orow[tid + 256] = o1; orow[tid + 512] = o2;

    float lm = fmaxf(fmaxf(fabsf(o0), fabsf(o1)), fabsf(o2));
#pragma unroll
    for (int o = 16; o > 0; o >>= 1) lm = fmaxf(lm, __shfl_xor_sync(0xffffffffu, lm, o));
    if (lane == 0) sm[wid] = lm;
    __syncthreads();
    if (tid == 0) {
        float t = sm[0];
#pragma unroll
        for (int k = 1; k < 8; k++) t = fmaxf(t, sm[k]);
        atomicMaxF(slot + (row & 31) * 64, t);
    }
}

// ---------------- bf16 HMMA GEMM, C = A[M,K] * B[N,K]^T ----------------
// Block 128x128, BK=64 (128B rows, XOR swizzle on 16B chunks), 3-stage cp.async
// with a single __syncthreads per k-iteration. Warp grid 4(M) x 2(N); warp tile
// 32x64 via mma.m16n8k16.bf16 (fp32 accum).
// EPI: 0 = bias, 1 = bias + residual, 2 = bias + exact GELU + fused absmax
template<int EPI>
__global__ __launch_bounds__(256, 2) void gemm_bf16_k(
    const __nv_bfloat16* __restrict__ A, const __nv_bfloat16* __restrict__ B,
    int M, int N, int K,
    const float* __restrict__ amaxA, int nA,
    const float* __restrict__ amaxB, int nB,
    const float* __restrict__ bias, const float* __restrict__ res,
    float* __restrict__ C, float* __restrict__ gmax)
{
    extern __shared__ __align__(1024) char smem[];   // 3 stages x (A 16KB + B 16KB)
    const uint32_t sbase = smem_u32(smem);
    const int tid  = threadIdx.x;
    const int lane = tid & 31, warp = tid >> 5;
    const int wm = warp & 3, wn = warp >> 2;
    const int m0 = blockIdx.y * 128, n0 = blockIdx.x * 128;
    const int gid = lane >> 2, tig = lane & 3;

    float acc[2][8][4];
#pragma unroll
    for (int mi = 0; mi < 2; mi++)
#pragma unroll
        for (int nj = 0; nj < 8; nj++)
#pragma unroll
            for (int r = 0; r < 4; r++) acc[mi][nj][r] = 0.0f;

    // global->smem mapping: thread t handles row t>>1, chunks (t&1)*4 .. +3 (16B each)
    const int lrow = tid >> 1, lcb = (tid & 1) * 4;
    const char* gA = (const char*)(A + (size_t)(m0 + lrow) * K) + lcb * 16;
    const char* gB = (const char*)(B + (size_t)(n0 + lrow) * K) + lcb * 16;
    uint32_t dst[4];
#pragma unroll
    for (int c = 0; c < 4; c++)
        dst[c] = lrow * 128 + (((lcb + c) ^ (lrow & 7)) << 4);

    // ldmatrix lane addressing (row-dependent swizzle s = row & 7 = lane & 7)
    const int s7 = lane & 7;
    uint32_t koff[4];
#pragma unroll
    for (int ks = 0; ks < 4; ks++) koff[ks] = ((ks * 2) ^ (s7 & 6)) << 4;
    const int rowA0 = wm * 32 + s7 + ((lane >> 3) & 1) * 8;
    const uint32_t aAb = rowA0 * 128 + (((((lane >> 4) & 1)) ^ (s7 & 1)) << 4);
    const int rowB0 = wn * 64 + s7 + ((lane >> 4) & 1) * 8;
    const uint32_t aBb = 16384 + rowB0 * 128 + (((((lane >> 3) & 1)) ^ (s7 & 1)) << 4);

    const int KT = K >> 6;   // >= 12 always

#define GISSUE(stg, ktile) do {                                          \
        const uint32_t so_ = (uint32_t)(stg) * 32768u;                   \
        const char* pA_ = gA + (size_t)(ktile) * 128;                    \
        const char* pB_ = gB + (size_t)(ktile) * 128;                    \
        _Pragma("unroll")                                                \
        for (int c_ = 0; c_ < 4; c_++) {                                 \
            cp16(sbase + so_ + dst[c_], pA_ + c_ * 16);                  \
            cp16(sbase + so_ + 16384 + dst[c_], pB_ + c_ * 16);          \
        }                                                                \
        asm volatile("cp.async.commit_group;\n");                        \
    } while (0)

    // prologue: stages 0 and 1 (groups 0, 1)
    GISSUE(0, 0);
    GISSUE(1, 1);

    int s_cur = 0, s_nxt = 2;
    for (int kt = 0; kt < KT; kt++) {
        if (kt < KT - 1) asm volatile("cp.async.wait_group 1;\n");
        else             asm volatile("cp.async.wait_group 0;\n");
        __syncthreads();
        // issue next tile into stage s_nxt (== stage (kt-1)%3, whose readers all
        // finished before the barrier above)
        if (kt + 2 < KT) GISSUE(s_nxt, kt + 2);

        const uint32_t so = (uint32_t)s_cur * 32768u;
#pragma unroll
        for (int ks = 0; ks < 4; ks++) {
            int a0[4], a1[4];
            ldsm4(sbase + so + aAb + koff[ks], a0);
            ldsm4(sbase + so + aAb + 2048 + koff[ks], a1);
#pragma unroll
            for (int p = 0; p < 4; p++) {
                int bf[4];
                ldsm4(sbase + so + aBb + p * 2048 + koff[ks], bf);
                mma_bf16(acc[0][2 * p],     a0, bf[0], bf[1]);
                mma_bf16(acc[1][2 * p],     a1, bf[0], bf[1]);
                mma_bf16(acc[0][2 * p + 1], a0, bf[2], bf[3]);
                mma_bf16(acc[1][2 * p + 1], a1, bf[2], bf[3]);
            }
        }
        if (++s_cur == 3) s_cur = 0;
        if (++s_nxt == 3) s_nxt = 0;
    }
#undef GISSUE

    // epilogue
    const float sa = __fdiv_rn(amax_get(amaxA, nA), 127.0f);
    const float sb = __fdiv_rn(amax_get(amaxB, nB), 127.0f);
    const float sc = sa * sb;
    float lmax = 0.0f;
#pragma unroll
    for (int mi = 0; mi < 2; mi++) {
        const int rowb = m0 + wm * 32 + mi * 16 + gid;
#pragma unroll
        for (int nj = 0; nj < 8; nj++) {
            const int col = n0 + wn * 64 + nj * 8 + 2 * tig;
            const float bi0 = bias[col], bi1 = bias[col + 1];
#pragma unroll
            for (int half = 0; half < 2; half++) {
                const int row = rowb + half * 8;
                const size_t off = (size_t)row * N + col;
                float v0 = acc[mi][nj][half * 2]     * sc + bi0;
                float v1 = acc[mi][nj][half * 2 + 1] * sc + bi1;
                if (EPI == 1) {
                    float2 rv = *reinterpret_cast<const float2*>(&res[off]);
                    v0 += rv.x; v1 += rv.y;
                }
                if (EPI == 2) {
                    v0 = 0.5f * v0 * (1.0f + erff(v0 * 0.70710678118654752440f));
                    v1 = 0.5f * v1 * (1.0f + erff(v1 * 0.70710678118654752440f));
                    lmax = fmaxf(lmax, fmaxf(fabsf(v0), fabsf(v1)));
                }
                *reinterpret_cast<float2*>(&C[off]) = make_float2(v0, v1);
            }
        }
    }
    if (EPI == 2) {
#pragma unroll
        for (int o = 16; o > 0; o >>= 1)
            lmax = fmaxf(lmax, __shfl_xor_sync(0xffffffffu, lmax, o));
        __shared__ float sred[8];
        if (lane == 0) sred[warp] = lmax;
        __syncthreads();
        if (tid == 0) {
            float t = sred[0];
#pragma unroll
            for (int k = 1; k < 8; k++) t = fmaxf(t, sred[k]);
            atomicMaxF(gmax + ((blockIdx.y * gridDim.x + blockIdx.x) & 31) * 64, t);
        }
    }
}

// ---------------- temporal attention: one block per (b, c, h) ----------------
__global__ __launch_bounds__(256) void attn_k(const float* __restrict__ qkv,
                                              float* __restrict__ o,
                                              float* __restrict__ slot) {
    __shared__ float sQ[64][64];   // Q, later reused for V
    __shared__ float sKt[64][64];  // K transposed + rotated: [d][(t+d)&63]
    __shared__ float sS[64][64];   // scores rotated: [t][(s+t)&63]
    int id = blockIdx.x, tid = threadIdx.x;
    int h = id % 12, c = (id / 12) & 63, b = id / (12 * 64);
    size_t base = ((size_t)(b * 4096 + c * 64)) * DQKV + h * 64;

    for (int i = tid; i < 1024; i += 256) {
        int t = i >> 4, c4 = (i & 15) * 4;
        float4 q4 = *reinterpret_cast<const float4*>(&qkv[base + (size_t)t * DQKV + c4]);
        *reinterpret_cast<float4*>(&sQ[t][c4]) = q4;
        float4 k4 = *reinterpret_cast<const float4*>(&qkv[base + (size_t)t * DQKV + 768 + c4]);
        sKt[c4 + 0][(t + c4 + 0) & 63] = k4.x;
        sKt[c4 + 1][(t + c4 + 1) & 63] = k4.y;
        sKt[c4 + 2][(t + c4 + 2) & 63] = k4.z;
        sKt[c4 + 3][(t + c4 + 3) & 63] = k4.w;
    }
    __syncthreads();

    int i4 = tid >> 4, j4 = tid & 15;
    {
        float acc[4][4];
#pragma unroll
        for (int i = 0; i < 4; i++)
#pragma unroll
            for (int j = 0; j < 4; j++) acc[i][j] = 0.0f;
#pragma unroll 4
        for (int d = 0; d < 64; d++) {
            float qa[4], kb[4];
#pragma unroll
            for (int i = 0; i < 4; i++) qa[i] = sQ[i4 * 4 + i][d];
#pragma unroll
            for (int j = 0; j < 4; j++) kb[j] = sKt[d][((j4 * 4 + j) + d) & 63];
#pragma unroll
            for (int i = 0; i < 4; i++)
#pragma unroll
                for (int j = 0; j < 4; j++) acc[i][j] = fmaf(qa[i], kb[j], acc[i][j]);
        }
#pragma unroll
        for (int i = 0; i < 4; i++) {
            int tt = i4 * 4 + i;
#pragma unroll
            for (int j = 0; j < 4; j++) {
                int ss = j4 * 4 + j;
                sS[tt][(ss + tt) & 63] = acc[i][j] * 0.125f;
            }
        }
    }
    __syncthreads();

    for (int i = tid; i < 1024; i += 256) {
        int t = i >> 4, c4 = (i & 15) * 4;
        float4 v4 = *reinterpret_cast<const float4*>(&qkv[base + (size_t)t * DQKV + 1536 + c4]);
        *reinterpret_cast<float4*>(&sQ[t][c4]) = v4;
    }
    if (tid < 64) {
        int r = tid;
        float m = -3.402823466e38f;
        for (int s = 0; s < 64; s++) m = fmaxf(m, sS[r][(s + r) & 63]);
        float sum = 0.0f;
        for (int s = 0; s < 64; s++) {
            float e = expf(sS[r][(s + r) & 63] - m);
            sS[r][(s + r) & 63] = e;
            sum += e;
        }
        float inv = __fdiv_rn(1.0f, sum);
        for (int s = 0; s < 64; s++) sS[r][(s + r) & 63] *= inv;
    }
    __syncthreads();

    float acc[4][4];
#pragma unroll
    for (int i = 0; i < 4; i++)
#pragma unroll
        for (int j = 0; j < 4; j++) acc[i][j] = 0.0f;
#pragma unroll 4
    for (int s = 0; s < 64; s++) {
        float pa[4], vb[4];
#pragma unroll
        for (int i = 0; i < 4; i++) { int tt = i4 * 4 + i; pa[i] = sS[tt][(s + tt) & 63]; }
#pragma unroll
        for (int j = 0; j < 4; j++) vb[j] = sQ[s][j4 * 4 + j];
#pragma unroll
        for (int i = 0; i < 4; i++)
#pragma unroll
            for (int j = 0; j < 4; j++) acc[i][j] = fmaf(pa[i], vb[j], acc[i][j]);
    }
    float lmax = 0.0f;
#pragma unroll
    for (int i = 0; i < 4; i++) {
        int tt = i4 * 4 + i;
        size_t orow = ((size_t)(b * 4096 + c * 64 + tt)) * DM + h * 64;
#pragma unroll
        for (int j = 0; j < 4; j++) {
            int dd = j4 * 4 + j;
            o[orow + dd] = acc[i][j];
            lmax = fmaxf(lmax, fabsf(acc[i][j]));
        }
    }
#pragma unroll
    for (int off = 16; off > 0; off >>= 1)
        lmax = fmaxf(lmax, __shfl_xor_sync(0xffffffffu, lmax, off));
    if ((tid & 31) == 0) atomicMaxF(slot + (blockIdx.x & 31) * 64, lmax);
}

// ---------------- launch ----------------
extern "C" void kernel_launch(void* const* d_in, const int* in_sizes, int n_in,
                              void* d_out, int out_size) {
    const float* x      = (const float*)d_in[0];
    const float* ln1_g  = (const float*)d_in[1];
    const float* ln1_b  = (const float*)d_in[2];
    const float* qkv_w  = (const float*)d_in[3];
    const float* qkv_b  = (const float*)d_in[4];
    const float* proj_w = (const float*)d_in[5];
    const float* proj_b = (const float*)d_in[6];
    const float* ln2_g  = (const float*)d_in[7];
    const float* ln2_b  = (const float*)d_in[8];
    const float* fc1_w  = (const float*)d_in[9];
    const float* fc1_b  = (const float*)d_in[10];
    const float* fc2_w  = (const float*)d_in[11];
    const float* fc2_b  = (const float*)d_in[12];

    float *pf, *pqkv, *px2, *pfc1, *pamax, *pslots;
    __nv_bfloat16 *pq, *pfc1q, *pwqkv, *pwproj, *pwfc1, *pwfc2;
    cudaGetSymbolAddress((void**)&pf,    g_f);
    cudaGetSymbolAddress((void**)&pqkv,  g_qkv);
    cudaGetSymbolAddress((void**)&px2,   g_x2);
    cudaGetSymbolAddress((void**)&pfc1,  g_fc1);
    cudaGetSymbolAddress((void**)&pq,    g_qb);
    cudaGetSymbolAddress((void**)&pfc1q, g_fc1q);
    cudaGetSymbolAddress((void**)&pwqkv, g_wqkv);
    cudaGetSymbolAddress((void**)&pwproj,g_wproj);
    cudaGetSymbolAddress((void**)&pwfc1, g_wfc1);
    cudaGetSymbolAddress((void**)&pwfc2, g_wfc2);
    cudaGetSymbolAddress((void**)&pamax, g_amax);
    cudaGetSymbolAddress((void**)&pslots,g_slots);

    const int SMEM = 3 * 32768;   // 3 stages x 32KB = 96KB
    cudaFuncSetAttribute(gemm_bf16_k<0>, cudaFuncAttributeMaxDynamicSharedMemorySize, SMEM);
    cudaFuncSetAttribute(gemm_bf16_k<1>, cudaFuncAttributeMaxDynamicSharedMemorySize, SMEM);
    cudaFuncSetAttribute(gemm_bf16_k<2>, cudaFuncAttributeMaxDynamicSharedMemorySize, SMEM);

    zero_k<<<8, 256>>>(pamax, pslots);

    absmax_w_k<<<dim3(128, 4), 256>>>(qkv_w, proj_w, fc1_w, fc2_w, pamax);
    quant_w_k<<<dim3(128, 4), 256>>>(qkv_w, proj_w, fc1_w, fc2_w,
                                     pwqkv, pwproj, pwfc1, pwfc2, pamax);

    // attn branch
    ln_k<<<NTOK, 256>>>(x, ln1_g, ln1_b, pf, pslots + 0 * 2048);
    quant_a_k<<<2048, 256>>>(pf, pq, NTOK * DM / 4, pslots + 0 * 2048);
    gemm_bf16_k<0><<<dim3(DQKV / 128, NTOK / 128), 256, SMEM>>>(
        pq, pwqkv, NTOK, DQKV, DM, pslots + 0 * 2048, 32, pamax + 4, 1,
        qkv_b, nullptr, pqkv, nullptr);
    attn_k<<<8 * 64 * 12, 256>>>(pqkv, pf, pslots + 1 * 2048);
    quant_a_k<<<2048, 256>>>(pf, pq, NTOK * DM / 4, pslots + 1 * 2048);
    gemm_bf16_k<1><<<dim3(DM / 128, NTOK / 128), 256, SMEM>>>(
        pq, pwproj, NTOK, DM, DM, pslots + 1 * 2048, 32, pamax + 5, 1,
        proj_b, x, px2, nullptr);

    // mlp branch
    ln_k<<<NTOK, 256>>>(px2, ln2_g, ln2_b, pf, pslots + 2 * 2048);
    quant_a_k<<<2048, 256>>>(pf, pq, NTOK * DM / 4, pslots + 2 * 2048);
    gemm_bf16_k<2><<<dim3(DFC / 128, NTOK / 128), 256, SMEM>>>(
        pq, pwfc1, NTOK, DFC, DM, pslots + 2 * 2048, 32, pamax + 6, 1,
        fc1_b, nullptr, pfc1, pslots + 3 * 2048);
    quant_a_k<<<4096, 256>>>(pfc1, pfc1q, NTOK * DFC / 4, pslots + 3 * 2048);
    gemm_bf16_k<1><<<dim3(DM / 128, NTOK / 128), 256, SMEM>>>(
        pfc1q, pwfc2, NTOK, DM, DFC, pslots + 3 * 2048, 32, pamax + 7, 1,
        fc2_b, px2, (float*)d_out, nullptr);
}